// round 9
// baseline (speedup 1.0000x reference)
#include <cuda_runtime.h>
#include <cuda_bf16.h>
#include <math.h>

#define TT 2048
#define BB 512
#define HH 128
#define GG 512
#define ROWS 8
#define NPAIR (BB / ROWS)   // 64 producer/consumer pairs
#define PADH 136            // h row stride (bf16)
#define XPAD 520            // xg stage/smem row stride (bf16)
#define PADW 136            // Wih1 smem row stride (bf16)
#define CHUNK 64            // producer publish granularity (steps)

typedef unsigned int u32;

// scratch (static device globals: allowed; no cudaMalloc anywhere)
static __device__ __nv_bfloat16 g_xg1[(size_t)BB * TT * GG];  // layer-1 input gates + bias (bf16)
static __device__ float g_h1f[BB * HH];                       // final hidden of layer 1
static __device__ u32 g_flag[NPAIR];                          // producer progress flags

__device__ __forceinline__ float tanha(float x) {
    asm("tanh.approx.f32 %0, %0;" : "+f"(x));
    return x;
}
__device__ __forceinline__ float sigm(float x) { return fmaf(tanha(0.5f * x), 0.5f, 0.5f); }

__device__ __forceinline__ u32 pbf2(float a, float b) {
    __nv_bfloat162 t = __floats2bfloat162_rn(a, b);
    return *(u32 *)&t;
}

__device__ __forceinline__ void mma16816(float *c, const u32 *a, const u32 *b) {
    asm volatile(
        "mma.sync.aligned.m16n8k16.row.col.f32.bf16.bf16.f32 "
        "{%0,%1,%2,%3}, {%4,%5,%6,%7}, {%8,%9}, {%0,%1,%2,%3};"
        : "+f"(c[0]), "+f"(c[1]), "+f"(c[2]), "+f"(c[3])
        : "r"(a[0]), "r"(a[1]), "r"(a[2]), "r"(a[3]), "r"(b[0]), "r"(b[1]));
}

__device__ __forceinline__ void ldmx4(u32 &r0, u32 &r1, u32 &r2, u32 &r3, u32 addr) {
    asm volatile("ldmatrix.sync.aligned.m8n8.x4.shared.b16 {%0,%1,%2,%3}, [%4];"
                 : "=r"(r0), "=r"(r1), "=r"(r2), "=r"(r3) : "r"(addr));
}

__device__ __forceinline__ u32 smem_u32(const void *p) {
    u32 a;
    asm("{ .reg .u64 t; cvta.to.shared.u64 t, %1; cvt.u32.u64 %0, t; }" : "=r"(a) : "l"(p));
    return a;
}

__device__ __forceinline__ u32 ld_acq(const u32 *p) {
    u32 v;
    asm volatile("ld.global.acquire.gpu.u32 %0, [%1];" : "=r"(v) : "l"(p) : "memory");
    return v;
}
__device__ __forceinline__ void st_rel(u32 *p, u32 v) {
    asm volatile("st.global.release.gpu.u32 [%0], %1;" :: "l"(p), "r"(v) : "memory");
}

// ============ producer: layer-0 LSTM + fused Wih1 GEMM, 512 threads / 16 warps ============
// Warp w owns units [w*8, w*8+8). Tile q=0: gates (i,f); q=1: gates (g,o).
__device__ __forceinline__ void producer(
    const float *__restrict__ x, const float *__restrict__ Wih0,
    const float *__restrict__ Whh0, const float *__restrict__ bih0,
    const float *__restrict__ bhh0, const float *__restrict__ Wih1,
    const float *__restrict__ bih1, const float *__restrict__ bhh1, char *smem) {
    __nv_bfloat16 *W1s = (__nv_bfloat16 *)smem;                    // [512][PADW] 139264 B
    __nv_bfloat16 *hbuf = (__nv_bfloat16 *)(smem + 139264);        // [2][8][PADH] 4352 B
    __nv_bfloat16 *stage = (__nv_bfloat16 *)(smem + 143616);       // [2][8][XPAD] 16640 B
    u32 *fslot = (u32 *)(smem + 160256);                           // [2][8] 64 B
    const int tid = threadIdx.x;
    const int w = tid >> 5, lane = tid & 31, gid = lane >> 2, tig = lane & 3;
    const int rb = blockIdx.x * ROWS;
    const int u = w * 8 + gid, r0 = 2 * tig, r1 = r0 + 1;

    // Whh0 A-frags + fold (tile q: rows q*256+u [gate 2q], q*256+128+u [gate 2q+1]) — R6-validated
    u32 a[2][8][4], af[2][2];
#pragma unroll
    for (int q = 0; q < 2; ++q) {
        const int ra = q * 256 + u, rbx = q * 256 + 128 + u;
#pragma unroll
        for (int kt = 0; kt < 8; ++kt) {
            const int k = kt * 16 + 2 * tig;
            a[q][kt][0] = pbf2(Whh0[(size_t)ra * HH + k], Whh0[(size_t)ra * HH + k + 1]);
            a[q][kt][1] = pbf2(Whh0[(size_t)rbx * HH + k], Whh0[(size_t)rbx * HH + k + 1]);
            a[q][kt][2] = pbf2(Whh0[(size_t)ra * HH + k + 8], Whh0[(size_t)ra * HH + k + 9]);
            a[q][kt][3] = pbf2(Whh0[(size_t)rbx * HH + k + 8], Whh0[(size_t)rbx * HH + k + 9]);
        }
        af[q][0] = (tig == 0) ? pbf2(Wih0[ra * 2], Wih0[ra * 2 + 1])
                              : (tig == 1 ? pbf2(bih0[ra] + bhh0[ra], 0.f) : 0u);
        af[q][1] = (tig == 0) ? pbf2(Wih0[rbx * 2], Wih0[rbx * 2 + 1])
                              : (tig == 1 ? pbf2(bih0[rbx] + bhh0[rbx], 0.f) : 0u);
    }
    // layer-1 input bias for this unit's 4 gates
    float bx[4];
#pragma unroll
    for (int g = 0; g < 4; ++g) bx[g] = bih1[g * 128 + u] + bhh1[g * 128 + u];

    // pack Wih1 into SMEM (bf16, PADW stride)
    for (int i = tid; i < 512 * 32; i += 512) {
        int row = i >> 5, kc = i & 31;
        float4 v = *(const float4 *)(Wih1 + (size_t)row * HH + kc * 4);
        *(__nv_bfloat162 *)&W1s[row * PADW + kc * 4] = __floats2bfloat162_rn(v.x, v.y);
        *(__nv_bfloat162 *)&W1s[row * PADW + kc * 4 + 2] = __floats2bfloat162_rn(v.z, v.w);
    }
    // ldmatrix lane addresses for the two gemm A-tiles (rows q*256+w*8 and q*256+128+w*8)
    const u32 w1b = smem_u32(W1s);
    u32 ldm[2];
#pragma unroll
    for (int q = 0; q < 2; ++q) {
        const int row_l = q * 256 + ((lane & 8) ? 128 : 0) + w * 8 + (lane & 7);
        ldm[q] = w1b + (u32)((row_l * PADW + ((lane & 16) ? 8 : 0)) * 2);
    }
    for (int i = tid; i < 2 * ROWS * PADH / 2; i += 512) ((u32 *)hbuf)[i] = 0u;
    if (tid < ROWS) {
        const float *xp = x + ((size_t)(rb + tid) * TT) * 6;
        fslot[tid] = pbf2(sqrtf(xp[0] * xp[0] + xp[1] * xp[1] + xp[2] * xp[2]),
                          sqrtf(xp[3] * xp[3] + xp[4] * xp[4] + xp[5] * xp[5]));
    }
    const u32 bfc = (tig == 1) ? pbf2(1.f, 0.f) : 0u;
    float c0 = 0.f, c1 = 0.f;
    u32 *myflag = &g_flag[blockIdx.x];
    __syncthreads();

#pragma unroll 1
    for (int t = 0; t <= TT; ++t) {
        const __nv_bfloat16 *hb = hbuf + (t & 1) * ROWS * PADH;  // h(t-1)
        u32 b[8][2];
#pragma unroll
        for (int kt = 0; kt < 8; ++kt) {
            const int base = gid * PADH + kt * 16 + 2 * tig;
            b[kt][0] = *(const u32 *)&hb[base];
            b[kt][1] = *(const u32 *)&hb[base + 8];
        }
        float pfx = 0.f, pfy = 0.f;
        const bool pfv = (tid < ROWS) && (t + 1 < TT);
        if (pfv) {
            const float *xp = x + ((size_t)(rb + tid) * TT + (t + 1)) * 6;
            pfx = sqrtf(xp[0] * xp[0] + xp[1] * xp[1] + xp[2] * xp[2]);
            pfy = sqrtf(xp[3] * xp[3] + xp[4] * xp[4] + xp[5] * xp[5]);
        }
        if (t < TT) {
            // ---- recurrence: h(t) ----
            const u32 bf0 = (tig == 0) ? fslot[(t & 1) * 8 + gid] : bfc;
            float acc[2][4];
            acc[0][0] = acc[0][1] = acc[0][2] = acc[0][3] = 0.f;
            acc[1][0] = acc[1][1] = acc[1][2] = acc[1][3] = 0.f;
#pragma unroll
            for (int kt = 0; kt < 8; ++kt) {
                mma16816(acc[0], a[0][kt], b[kt]);
                mma16816(acc[1], a[1][kt], b[kt]);
            }
            {
                u32 bfr[2] = {bf0, 0u};
#pragma unroll
                for (int q = 0; q < 2; ++q) {
                    u32 afr[4] = {af[q][0], af[q][1], 0u, 0u};
                    mma16816(acc[q], afr, bfr);
                }
            }
            __nv_bfloat16 *hn = hbuf + ((t + 1) & 1) * ROWS * PADH;
            // tile0: i@r0,i@r1,f@r0,f@r1 ; tile1: g,o
            c0 = sigm(acc[0][2]) * c0 + sigm(acc[0][0]) * tanha(acc[1][0]);
            const float h0 = sigm(acc[1][2]) * tanha(c0);
            c1 = sigm(acc[0][3]) * c1 + sigm(acc[0][1]) * tanha(acc[1][1]);
            const float h1 = sigm(acc[1][3]) * tanha(c1);
            hn[r0 * PADH + u] = __float2bfloat16(h0);
            hn[r1 * PADH + u] = __float2bfloat16(h1);
            if (pfv) fslot[((t + 1) & 1) * 8 + tid] = pbf2(pfx, pfy);
        }
        if (t > 0) {
            // ---- fused GEMM: xg(t-1) = Wih1 @ h(t-1) + bias (reuses b-frags) ----
            float xa[2][4];
            xa[0][0] = xa[0][1] = xa[0][2] = xa[0][3] = 0.f;
            xa[1][0] = xa[1][1] = xa[1][2] = xa[1][3] = 0.f;
#pragma unroll
            for (int kt = 0; kt < 8; ++kt) {
                u32 aw[4];
                ldmx4(aw[0], aw[1], aw[2], aw[3], ldm[0] + kt * 32);
                mma16816(xa[0], aw, b[kt]);
                ldmx4(aw[0], aw[1], aw[2], aw[3], ldm[1] + kt * 32);
                mma16816(xa[1], aw, b[kt]);
            }
            __nv_bfloat16 *stg = stage + (t & 1) * ROWS * XPAD;
            // xa[0]: i@r0, i@r1, f@r0, f@r1 ; xa[1]: g, o
            stg[r0 * XPAD + u] = __float2bfloat16(xa[0][0] + bx[0]);
            stg[r1 * XPAD + u] = __float2bfloat16(xa[0][1] + bx[0]);
            stg[r0 * XPAD + 128 + u] = __float2bfloat16(xa[0][2] + bx[1]);
            stg[r1 * XPAD + 128 + u] = __float2bfloat16(xa[0][3] + bx[1]);
            stg[r0 * XPAD + 256 + u] = __float2bfloat16(xa[1][0] + bx[2]);
            stg[r1 * XPAD + 256 + u] = __float2bfloat16(xa[1][1] + bx[2]);
            stg[r0 * XPAD + 384 + u] = __float2bfloat16(xa[1][2] + bx[3]);
            stg[r1 * XPAD + 384 + u] = __float2bfloat16(xa[1][3] + bx[3]);
        }
        __syncthreads();
        if (t > 0) {
            // coalesced xg(t-1) store: 512 threads x uint4 = 8KB
            const __nv_bfloat16 *stg = stage + (t & 1) * ROWS * XPAD;
            const int row = tid >> 6, seg = tid & 63;
            uint4 v = *(const uint4 *)&stg[row * XPAD + seg * 8];
            *(uint4 *)(g_xg1 + ((size_t)(rb + row) * TT + (t - 1)) * GG + seg * 8) = v;
            if ((t & (CHUNK - 1)) == 0) {  // publish every CHUNK steps
                __threadfence();
                __syncthreads();
                if (tid == 0) st_rel(myflag, (u32)t);
            }
        }
    }
}

// ============ consumer: layer-1 LSTM, 512 threads, chunk-granular poll ============
__device__ __forceinline__ void consumer(const float *__restrict__ Whh1, char *smem) {
    __nv_bfloat16 *hbuf = (__nv_bfloat16 *)smem;                 // [2][8][PADH] 4352 B
    __nv_bfloat16 *xbuf = (__nv_bfloat16 *)(smem + 4352);        // [2][8][XPAD] 16640 B
    const int tid = threadIdx.x;
    const int w = tid >> 5, lane = tid & 31, gid = lane >> 2, tig = lane & 3;
    const int p = blockIdx.x - NPAIR;
    const int rb = p * ROWS;
    const int u = w * 8 + gid, r0 = 2 * tig, r1 = r0 + 1;
    const u32 *myflag = &g_flag[p];

    u32 a[2][8][4];
#pragma unroll
    for (int q = 0; q < 2; ++q) {
        const int ra = q * 256 + u, rbx = q * 256 + 128 + u;
#pragma unroll
        for (int kt = 0; kt < 8; ++kt) {
            const int k = kt * 16 + 2 * tig;
            a[q][kt][0] = pbf2(Whh1[(size_t)ra * HH + k], Whh1[(size_t)ra * HH + k + 1]);
            a[q][kt][1] = pbf2(Whh1[(size_t)rbx * HH + k], Whh1[(size_t)rbx * HH + k + 1]);
            a[q][kt][2] = pbf2(Whh1[(size_t)ra * HH + k + 8], Whh1[(size_t)ra * HH + k + 9]);
            a[q][kt][3] = pbf2(Whh1[(size_t)rbx * HH + k + 8], Whh1[(size_t)rbx * HH + k + 9]);
        }
    }
    for (int i = tid; i < 2 * ROWS * PADH / 2; i += 512) ((u32 *)hbuf)[i] = 0u;
    const int xrow = tid >> 6, xcol = tid & 63;
    u32 seen = ld_acq(myflag);
    while (seen < 1u) { __nanosleep(256); seen = ld_acq(myflag); }
    {
        uint4 v = *(const uint4 *)(g_xg1 + ((size_t)(rb + xrow) * TT) * GG + xcol * 8);
        *(uint4 *)&xbuf[xrow * XPAD + xcol * 8] = v;
    }
    float c0 = 0.f, c1 = 0.f;
    __syncthreads();

#pragma unroll 1
    for (int t = 0; t < TT; ++t) {
        const int hasn = (t + 1 < TT);
        uint4 pf;
        if (hasn) {
            const u32 need = (u32)(t + 2);
            if (seen < need) {
                seen = ld_acq(myflag);
                while (seen < need) { __nanosleep(128); seen = ld_acq(myflag); }
            }
            pf = *(const uint4 *)(g_xg1 + ((size_t)(rb + xrow) * TT + (t + 1)) * GG + xcol * 8);
        }
        const __nv_bfloat16 *xb = xbuf + (t & 1) * ROWS * XPAD;
        const __nv_bfloat16 *hb = hbuf + (t & 1) * ROWS * PADH;
        __nv_bfloat16 *hn = hbuf + ((t + 1) & 1) * ROWS * PADH;
        u32 b[8][2];
#pragma unroll
        for (int kt = 0; kt < 8; ++kt) {
            const int base = gid * PADH + kt * 16 + 2 * tig;
            b[kt][0] = *(const u32 *)&hb[base];
            b[kt][1] = *(const u32 *)&hb[base + 8];
        }
        float acc[2][4];
        acc[0][0] = acc[0][1] = acc[0][2] = acc[0][3] = 0.f;
        acc[1][0] = acc[1][1] = acc[1][2] = acc[1][3] = 0.f;
#pragma unroll
        for (int kt = 0; kt < 8; ++kt) {
            mma16816(acc[0], a[0][kt], b[kt]);
            mma16816(acc[1], a[1][kt], b[kt]);
        }
        const float gi0 = acc[0][0] + __bfloat162float(xb[r0 * XPAD + u]);
        const float gi1 = acc[0][1] + __bfloat162float(xb[r1 * XPAD + u]);
        const float gf0 = acc[0][2] + __bfloat162float(xb[r0 * XPAD + 128 + u]);
        const float gf1 = acc[0][3] + __bfloat162float(xb[r1 * XPAD + 128 + u]);
        const float gg0 = acc[1][0] + __bfloat162float(xb[r0 * XPAD + 256 + u]);
        const float gg1 = acc[1][1] + __bfloat162float(xb[r1 * XPAD + 256 + u]);
        const float go0 = acc[1][2] + __bfloat162float(xb[r0 * XPAD + 384 + u]);
        const float go1 = acc[1][3] + __bfloat162float(xb[r1 * XPAD + 384 + u]);
        c0 = sigm(gf0) * c0 + sigm(gi0) * tanha(gg0);
        const float h0 = sigm(go0) * tanha(c0);
        c1 = sigm(gf1) * c1 + sigm(gi1) * tanha(gg1);
        const float h1 = sigm(go1) * tanha(c1);
        hn[r0 * PADH + u] = __float2bfloat16(h0);
        hn[r1 * PADH + u] = __float2bfloat16(h1);
        if (hasn) {
            __nv_bfloat16 *xn = xbuf + ((t + 1) & 1) * ROWS * XPAD;
            *(uint4 *)&xn[xrow * XPAD + xcol * 8] = pf;
        } else {
            g_h1f[(rb + r0) * HH + u] = h0;
            g_h1f[(rb + r1) * HH + u] = h1;
        }
        __syncthreads();
    }
}

extern "C" __global__ void __launch_bounds__(512, 1)
k_pipe(const float *__restrict__ x, const float *__restrict__ Wih0,
       const float *__restrict__ Whh0, const float *__restrict__ bih0,
       const float *__restrict__ bhh0, const float *__restrict__ Wih1,
       const float *__restrict__ Whh1, const float *__restrict__ bih1,
       const float *__restrict__ bhh1) {
    extern __shared__ char smem[];
    if (blockIdx.x < NPAIR)
        producer(x, Wih0, Whh0, bih0, bhh0, Wih1, bih1, bhh1, smem);
    else
        consumer(Whh1, smem);
}

extern "C" __global__ void k_reset() {
    if (threadIdx.x < NPAIR) g_flag[threadIdx.x] = 0u;
}

// ================= classifier MLP + double softmax =================
extern "C" __global__ void __launch_bounds__(128)
k_cls(const float *__restrict__ W1, const float *__restrict__ b1,
      const float *__restrict__ W2, const float *__restrict__ b2,
      const float *__restrict__ W3, const float *__restrict__ b3,
      float *__restrict__ out) {
    __shared__ float hb[128], z1[128], z2[64], z3[8];
    const int tid = threadIdx.x;
    const int row = blockIdx.x;
    hb[tid] = g_h1f[row * HH + tid];
    __syncthreads();
    float a = b1[tid];
#pragma unroll 4
    for (int k = 0; k < 128; ++k) a = fmaf(W1[tid * 128 + k], hb[k], a);
    z1[tid] = fmaxf(a, 0.f);
    __syncthreads();
    if (tid < 64) {
        float s = b2[tid];
#pragma unroll 4
        for (int k = 0; k < 128; ++k) s = fmaf(W2[tid * 128 + k], z1[k], s);
        z2[tid] = fmaxf(s, 0.f);
    }
    __syncthreads();
    if (tid < 6) {
        float s = b3[tid];
#pragma unroll 4
        for (int k = 0; k < 64; ++k) s = fmaf(W3[tid * 64 + k], z2[k], s);
        z3[tid] = s;
    }
    __syncthreads();
    if (tid == 0) {
        float v[6];
#pragma unroll
        for (int i = 0; i < 6; ++i) v[i] = z3[i];
#pragma unroll
        for (int p = 0; p < 2; ++p) {
            float m = v[0];
            for (int i = 1; i < 6; ++i) m = fmaxf(m, v[i]);
            float s = 0.f;
            for (int i = 0; i < 6; ++i) { v[i] = expf(v[i] - m); s += v[i]; }
            float inv = 1.f / s;
            for (int i = 0; i < 6; ++i) v[i] *= inv;
        }
        for (int i = 0; i < 6; ++i) out[row * 6 + i] = v[i];
    }
}

extern "C" void kernel_launch(void *const *d_in, const int *in_sizes, int n_in,
                              void *d_out, int out_size) {
    const float *x = (const float *)d_in[0];
    const float *Wih0 = (const float *)d_in[1];
    const float *Whh0 = (const float *)d_in[2];
    const float *bih0 = (const float *)d_in[3];
    const float *bhh0 = (const float *)d_in[4];
    const float *Wih1 = (const float *)d_in[5];
    const float *Whh1 = (const float *)d_in[6];
    const float *bih1 = (const float *)d_in[7];
    const float *bhh1 = (const float *)d_in[8];
    const float *W1 = (const float *)d_in[9];
    const float *b1 = (const float *)d_in[10];
    const float *W2 = (const float *)d_in[11];
    const float *b2 = (const float *)d_in[12];
    const float *W3 = (const float *)d_in[13];
    const float *b3 = (const float *)d_in[14];
    float *out = (float *)d_out;

    const int SMEMP = 139264 + 4352 + 16640 + 64;  // 160320 (producer layout; consumers use prefix)
    cudaFuncSetAttribute(k_pipe, cudaFuncAttributeMaxDynamicSharedMemorySize, SMEMP);

    k_reset<<<1, 64>>>();
    k_pipe<<<2 * NPAIR, 512, SMEMP>>>(x, Wih0, Whh0, bih0, bhh0, Wih1, Whh1, bih1, bhh1);
    k_cls<<<BB, 128>>>(W1, b1, W2, b2, W3, b3, out);
}

// round 10
// speedup vs baseline: 1.1877x; 1.1877x over previous
#include <cuda_runtime.h>
#include <cuda_bf16.h>
#include <math.h>

#define TT 2048
#define BB 512
#define HH 128
#define ROWS 8
#define NPAIR (BB / ROWS)   // 64 producer/consumer pairs
#define PADH 136            // h row stride (bf16)
#define XPI 264             // xg_if row stride (bf16), 256 data + pad
#define PADW 136            // Wih1-half smem row stride (bf16)
#define CHUNK 64            // publish granularity (steps)

typedef unsigned int u32;

// scratch (static device globals: allowed; no cudaMalloc anywhere)
static __device__ __nv_bfloat16 g_xgif[(size_t)BB * TT * 256];  // gates i,f of layer-1 input (+bias)
static __device__ __nv_bfloat16 g_h0[(size_t)BB * TT * HH];     // layer-0 hidden states
static __device__ float g_h1f[BB * HH];                         // final hidden of layer 1
static __device__ u32 g_flag[NPAIR];                            // producer progress flags

__device__ __forceinline__ float tanha(float x) {
    asm("tanh.approx.f32 %0, %0;" : "+f"(x));
    return x;
}
__device__ __forceinline__ float sigm(float x) { return fmaf(tanha(0.5f * x), 0.5f, 0.5f); }

__device__ __forceinline__ u32 pbf2(float a, float b) {
    __nv_bfloat162 t = __floats2bfloat162_rn(a, b);
    return *(u32 *)&t;
}

__device__ __forceinline__ void mma16816(float *c, const u32 *a, const u32 *b) {
    asm volatile(
        "mma.sync.aligned.m16n8k16.row.col.f32.bf16.bf16.f32 "
        "{%0,%1,%2,%3}, {%4,%5,%6,%7}, {%8,%9}, {%0,%1,%2,%3};"
        : "+f"(c[0]), "+f"(c[1]), "+f"(c[2]), "+f"(c[3])
        : "r"(a[0]), "r"(a[1]), "r"(a[2]), "r"(a[3]), "r"(b[0]), "r"(b[1]));
}

__device__ __forceinline__ void ldmx4(u32 &r0, u32 &r1, u32 &r2, u32 &r3, u32 addr) {
    asm volatile("ldmatrix.sync.aligned.m8n8.x4.shared.b16 {%0,%1,%2,%3}, [%4];"
                 : "=r"(r0), "=r"(r1), "=r"(r2), "=r"(r3) : "r"(addr));
}

__device__ __forceinline__ u32 smem_u32(const void *p) {
    u32 a;
    asm("{ .reg .u64 t; cvta.to.shared.u64 t, %1; cvt.u32.u64 %0, t; }" : "=r"(a) : "l"(p));
    return a;
}

__device__ __forceinline__ u32 ld_acq(const u32 *p) {
    u32 v;
    asm volatile("ld.global.acquire.gpu.u32 %0, [%1];" : "=r"(v) : "l"(p) : "memory");
    return v;
}
__device__ __forceinline__ void st_rel(u32 *p, u32 v) {
    asm volatile("st.global.release.gpu.u32 [%0], %1;" :: "l"(p), "r"(v) : "memory");
}

// ============ producer: layer-0 LSTM + gemm for gates (i,f) only. 256 threads / 8 warps ============
// Warp w owns units [w*16, w*16+16); rec A-tiles g=0..3 = gates i,f,g,o (R5/R7-validated layout).
__device__ __forceinline__ void producer(
    const float *__restrict__ x, const float *__restrict__ Wih0,
    const float *__restrict__ Whh0, const float *__restrict__ bih0,
    const float *__restrict__ bhh0, const float *__restrict__ Wih1,
    const float *__restrict__ bih1, const float *__restrict__ bhh1, char *smem) {
    __nv_bfloat16 *W1s = (__nv_bfloat16 *)smem;                    // [256][PADW] 69632 B (Wih1 rows 0..255)
    __nv_bfloat16 *hbuf = (__nv_bfloat16 *)(smem + 69632);         // [2][8][PADH] 4352 B
    __nv_bfloat16 *stage = (__nv_bfloat16 *)(smem + 73984);        // [2][8][XPI] 8448 B
    u32 *fslot = (u32 *)(smem + 82432);                            // [2][8] 64 B
    const int tid = threadIdx.x;
    const int w = tid >> 5, lane = tid & 31, gid = lane >> 2, tig = lane & 3;
    const int rb = blockIdx.x * ROWS;
    const int u0 = w * 16 + gid, u1 = u0 + 8;
    const int r0 = 2 * tig, r1 = r0 + 1;

    // Whh0 A-fragments + fold column (Wih0 | bias)
    u32 a[4][8][4], af0[4], af1[4];
#pragma unroll
    for (int g = 0; g < 4; ++g) {
        const int gr0 = g * 128 + u0, gr1 = g * 128 + u1;
#pragma unroll
        for (int kt = 0; kt < 8; ++kt) {
            const int k = kt * 16 + 2 * tig;
            a[g][kt][0] = pbf2(Whh0[(size_t)gr0 * HH + k], Whh0[(size_t)gr0 * HH + k + 1]);
            a[g][kt][1] = pbf2(Whh0[(size_t)gr1 * HH + k], Whh0[(size_t)gr1 * HH + k + 1]);
            a[g][kt][2] = pbf2(Whh0[(size_t)gr0 * HH + k + 8], Whh0[(size_t)gr0 * HH + k + 9]);
            a[g][kt][3] = pbf2(Whh0[(size_t)gr1 * HH + k + 8], Whh0[(size_t)gr1 * HH + k + 9]);
        }
        af0[g] = (tig == 0) ? pbf2(Wih0[gr0 * 2], Wih0[gr0 * 2 + 1])
                            : (tig == 1 ? pbf2(bih0[gr0] + bhh0[gr0], 0.f) : 0u);
        af1[g] = (tig == 0) ? pbf2(Wih0[gr1 * 2], Wih0[gr1 * 2 + 1])
                            : (tig == 1 ? pbf2(bih0[gr1] + bhh0[gr1], 0.f) : 0u);
    }
    // layer-1 input biases for gates i,f at this thread's units
    float bxa[2], bxb[2];
#pragma unroll
    for (int q = 0; q < 2; ++q) {
        bxa[q] = bih1[q * 128 + u0] + bhh1[q * 128 + u0];
        bxb[q] = bih1[q * 128 + u1] + bhh1[q * 128 + u1];
    }
    // pack Wih1 rows 0..255 (gates i,f) into SMEM
    for (int i = tid; i < 256 * 32; i += 256) {
        int row = i >> 5, kc = i & 31;
        float4 v = *(const float4 *)(Wih1 + (size_t)row * HH + kc * 4);
        *(__nv_bfloat162 *)&W1s[row * PADW + kc * 4] = __floats2bfloat162_rn(v.x, v.y);
        *(__nv_bfloat162 *)&W1s[row * PADW + kc * 4 + 2] = __floats2bfloat162_rn(v.z, v.w);
    }
    const u32 w1b = smem_u32(W1s);
    u32 ldm[2];
#pragma unroll
    for (int q = 0; q < 2; ++q) {
        const int row_l = q * 128 + w * 16 + (lane & 15);
        ldm[q] = w1b + (u32)((row_l * PADW + ((lane & 16) ? 8 : 0)) * 2);
    }
    for (int i = tid; i < 2 * ROWS * PADH / 2; i += 256) ((u32 *)hbuf)[i] = 0u;
    if (tid < ROWS) {
        const float *xp = x + ((size_t)(rb + tid) * TT) * 6;
        fslot[tid] = pbf2(sqrtf(xp[0] * xp[0] + xp[1] * xp[1] + xp[2] * xp[2]),
                          sqrtf(xp[3] * xp[3] + xp[4] * xp[4] + xp[5] * xp[5]));
    }
    const u32 bfc = (tig == 1) ? pbf2(1.f, 0.f) : 0u;
    float cst[4] = {0.f, 0.f, 0.f, 0.f};
    u32 *myflag = &g_flag[blockIdx.x];
    __syncthreads();

#pragma unroll 1
    for (int t = 0; t <= TT; ++t) {
        const __nv_bfloat16 *hb = hbuf + (t & 1) * ROWS * PADH;          // h(t-1)
        __nv_bfloat16 *hn = hbuf + ((t + 1) & 1) * ROWS * PADH;          // h(t)
        u32 b[8][2];
#pragma unroll
        for (int kt = 0; kt < 8; ++kt) {
            const int base = gid * PADH + kt * 16 + 2 * tig;
            b[kt][0] = *(const u32 *)&hb[base];
            b[kt][1] = *(const u32 *)&hb[base + 8];
        }
        float pfx = 0.f, pfy = 0.f;
        const bool pfv = (tid < ROWS) && (t + 1 < TT);
        if (pfv) {
            const float *xp = x + ((size_t)(rb + tid) * TT + (t + 1)) * 6;
            pfx = sqrtf(xp[0] * xp[0] + xp[1] * xp[1] + xp[2] * xp[2]);
            pfy = sqrtf(xp[3] * xp[3] + xp[4] * xp[4] + xp[5] * xp[5]);
        }
        if (t < TT) {
            // ---- recurrence: h(t) ----
            const u32 bf0 = (tig == 0) ? fslot[(t & 1) * 8 + gid] : bfc;
            float acc[4][4];
#pragma unroll
            for (int g = 0; g < 4; ++g) { acc[g][0] = acc[g][1] = acc[g][2] = acc[g][3] = 0.f; }
#pragma unroll
            for (int kt = 0; kt < 8; ++kt)
#pragma unroll
                for (int g = 0; g < 4; ++g) mma16816(acc[g], a[g][kt], b[kt]);
#pragma unroll
            for (int g = 0; g < 4; ++g) {
                u32 afr[4] = {af0[g], af1[g], 0u, 0u};
                u32 bfr[2] = {bf0, 0u};
                mma16816(acc[g], afr, bfr);
            }
            float h[4];
#pragma unroll
            for (int s = 0; s < 4; ++s) {
                cst[s] = sigm(acc[1][s]) * cst[s] + sigm(acc[0][s]) * tanha(acc[2][s]);
                h[s] = sigm(acc[3][s]) * tanha(cst[s]);
            }
            hn[r0 * PADH + u0] = __float2bfloat16(h[0]);
            hn[r1 * PADH + u0] = __float2bfloat16(h[1]);
            hn[r0 * PADH + u1] = __float2bfloat16(h[2]);
            hn[r1 * PADH + u1] = __float2bfloat16(h[3]);
            if (pfv) fslot[((t + 1) & 1) * 8 + tid] = pbf2(pfx, pfy);
        }
        if (t > 0) {
            // ---- gemm (gates i,f): xg_if(t-1) = Wih1[0:256] @ h(t-1) + bias ----
            float xa[2][4];
            xa[0][0] = xa[0][1] = xa[0][2] = xa[0][3] = 0.f;
            xa[1][0] = xa[1][1] = xa[1][2] = xa[1][3] = 0.f;
#pragma unroll
            for (int kt = 0; kt < 8; ++kt) {
                u32 aw[4];
                ldmx4(aw[0], aw[1], aw[2], aw[3], ldm[0] + kt * 32);
                mma16816(xa[0], aw, b[kt]);
                ldmx4(aw[0], aw[1], aw[2], aw[3], ldm[1] + kt * 32);
                mma16816(xa[1], aw, b[kt]);
            }
            __nv_bfloat16 *stg = stage + (t & 1) * ROWS * XPI;
#pragma unroll
            for (int q = 0; q < 2; ++q) {
                stg[r0 * XPI + q * 128 + u0] = __float2bfloat16(xa[q][0] + bxa[q]);
                stg[r1 * XPI + q * 128 + u0] = __float2bfloat16(xa[q][1] + bxa[q]);
                stg[r0 * XPI + q * 128 + u1] = __float2bfloat16(xa[q][2] + bxb[q]);
                stg[r1 * XPI + q * 128 + u1] = __float2bfloat16(xa[q][3] + bxb[q]);
            }
        }
        __syncthreads();
        // publish h0(t) (from completed hn tile; safe until overwritten at t+2, after t+1's barrier)
        if (t < TT && tid < 128) {
            const int row = tid >> 4, q = tid & 15;
            uint4 v = *(const uint4 *)&hn[row * PADH + q * 8];
            *(uint4 *)(g_h0 + ((size_t)(rb + row) * TT + t) * HH + q * 8) = v;
        }
        if (t > 0) {
            // coalesced xg_if(t-1) store: 256 threads x uint4 = 4KB
            const __nv_bfloat16 *stg = stage + (t & 1) * ROWS * XPI;
            const int row = tid >> 5, seg = tid & 31;
            uint4 v = *(const uint4 *)&stg[row * XPI + seg * 8];
            *(uint4 *)(g_xgif + ((size_t)(rb + row) * TT + (t - 1)) * 256 + seg * 8) = v;
            if ((t & (CHUNK - 1)) == 0) {  // publish every CHUNK steps
                __threadfence();
                __syncthreads();
                if (tid == 0) st_rel(myflag, (u32)t);
            }
        }
    }
}

// ===== consumer: layer-1 LSTM + gemm for gates (g,o) computed locally from h0. 256 threads =====
__device__ __forceinline__ void consumer(
    const float *__restrict__ Whh1, const float *__restrict__ Wih1,
    const float *__restrict__ bih1, const float *__restrict__ bhh1, char *smem) {
    __nv_bfloat16 *hbuf = (__nv_bfloat16 *)smem;                   // [2][8][PADH] 4352 B
    __nv_bfloat16 *h0buf = (__nv_bfloat16 *)(smem + 4352);         // [2][8][PADH] 4352 B
    __nv_bfloat16 *xifbuf = (__nv_bfloat16 *)(smem + 8704);        // [2][8][XPI] 8448 B
    __nv_bfloat16 *W1s = (__nv_bfloat16 *)(smem + 17152);          // [256][PADW] 69632 B (Wih1 rows 256..511)
    const int tid = threadIdx.x;
    const int w = tid >> 5, lane = tid & 31, gid = lane >> 2, tig = lane & 3;
    const int p = blockIdx.x - NPAIR;
    const int rb = p * ROWS;
    const int u0 = w * 16 + gid, u1 = u0 + 8;
    const int r0 = 2 * tig, r1 = r0 + 1;
    const u32 *myflag = &g_flag[p];

    // Whh1 A-fragments
    u32 a[4][8][4];
#pragma unroll
    for (int g = 0; g < 4; ++g) {
        const int gr0 = g * 128 + u0, gr1 = g * 128 + u1;
#pragma unroll
        for (int kt = 0; kt < 8; ++kt) {
            const int k = kt * 16 + 2 * tig;
            a[g][kt][0] = pbf2(Whh1[(size_t)gr0 * HH + k], Whh1[(size_t)gr0 * HH + k + 1]);
            a[g][kt][1] = pbf2(Whh1[(size_t)gr1 * HH + k], Whh1[(size_t)gr1 * HH + k + 1]);
            a[g][kt][2] = pbf2(Whh1[(size_t)gr0 * HH + k + 8], Whh1[(size_t)gr0 * HH + k + 9]);
            a[g][kt][3] = pbf2(Whh1[(size_t)gr1 * HH + k + 8], Whh1[(size_t)gr1 * HH + k + 9]);
        }
    }
    // biases for gates g,o at this thread's units
    float bg0 = bih1[256 + u0] + bhh1[256 + u0];
    float bg1 = bih1[256 + u1] + bhh1[256 + u1];
    float bo0 = bih1[384 + u0] + bhh1[384 + u0];
    float bo1 = bih1[384 + u1] + bhh1[384 + u1];
    // pack Wih1 rows 256..511 (gates g,o) into SMEM
    for (int i = tid; i < 256 * 32; i += 256) {
        int row = i >> 5, kc = i & 31;
        float4 v = *(const float4 *)(Wih1 + (size_t)(256 + row) * HH + kc * 4);
        *(__nv_bfloat162 *)&W1s[row * PADW + kc * 4] = __floats2bfloat162_rn(v.x, v.y);
        *(__nv_bfloat162 *)&W1s[row * PADW + kc * 4 + 2] = __floats2bfloat162_rn(v.z, v.w);
    }
    const u32 w1b = smem_u32(W1s);
    u32 ldm[2];
#pragma unroll
    for (int q = 0; q < 2; ++q) {
        const int row_l = q * 128 + w * 16 + (lane & 15);
        ldm[q] = w1b + (u32)((row_l * PADW + ((lane & 16) ? 8 : 0)) * 2);
    }
    for (int i = tid; i < 2 * ROWS * PADH / 2; i += 256) ((u32 *)hbuf)[i] = 0u;
    const int xrow = tid >> 5, xseg = tid & 31;   // xif tile: 8 rows x 32 segs
    const int hrow = tid >> 4, hseg = tid & 15;   // h0 tile: 8 rows x 16 segs (tid<128)
    u32 seen = ld_acq(myflag);
    while (seen < 1u) { __nanosleep(256); seen = ld_acq(myflag); }
    {   // prologue: xif(0) + h0(0) into buffer 0
        uint4 v = *(const uint4 *)(g_xgif + ((size_t)(rb + xrow) * TT) * 256 + xseg * 8);
        *(uint4 *)&xifbuf[xrow * XPI + xseg * 8] = v;
        if (tid < 128) {
            uint4 hv = *(const uint4 *)(g_h0 + ((size_t)(rb + hrow) * TT) * HH + hseg * 8);
            *(uint4 *)&h0buf[hrow * PADH + hseg * 8] = hv;
        }
    }
    float cst[4] = {0.f, 0.f, 0.f, 0.f};
    __syncthreads();

#pragma unroll 1
    for (int t = 0; t < TT; ++t) {
        const int hasn = (t + 1 < TT);
        uint4 pfx, pfh;
        if (hasn) {
            const u32 need = (u32)(t + 2);
            if (seen < need) {
                seen = ld_acq(myflag);
                while (seen < need) { __nanosleep(128); seen = ld_acq(myflag); }
            }
            pfx = *(const uint4 *)(g_xgif + ((size_t)(rb + xrow) * TT + (t + 1)) * 256 + xseg * 8);
            if (tid < 128)
                pfh = *(const uint4 *)(g_h0 + ((size_t)(rb + hrow) * TT + (t + 1)) * HH + hseg * 8);
        }
        const __nv_bfloat16 *xb = xifbuf + (t & 1) * ROWS * XPI;
        const __nv_bfloat16 *hb = hbuf + (t & 1) * ROWS * PADH;
        const __nv_bfloat16 *h0b = h0buf + (t & 1) * ROWS * PADH;
        __nv_bfloat16 *hn = hbuf + ((t + 1) & 1) * ROWS * PADH;
        u32 b[8][2], b0[8][2];
#pragma unroll
        for (int kt = 0; kt < 8; ++kt) {
            const int base = gid * PADH + kt * 16 + 2 * tig;
            b[kt][0] = *(const u32 *)&hb[base];
            b[kt][1] = *(const u32 *)&hb[base + 8];
            b0[kt][0] = *(const u32 *)&h0b[base];
            b0[kt][1] = *(const u32 *)&h0b[base + 8];
        }
        float acc[4][4];
#pragma unroll
        for (int g = 0; g < 4; ++g) { acc[g][0] = acc[g][1] = acc[g][2] = acc[g][3] = 0.f; }
#pragma unroll
        for (int kt = 0; kt < 8; ++kt)
#pragma unroll
            for (int g = 0; g < 4; ++g) mma16816(acc[g], a[g][kt], b[kt]);
        // gemm (gates g,o): xg_go(t) = Wih1[256:512] @ h0(t)
        float xa[2][4];
        xa[0][0] = xa[0][1] = xa[0][2] = xa[0][3] = 0.f;
        xa[1][0] = xa[1][1] = xa[1][2] = xa[1][3] = 0.f;
#pragma unroll
        for (int kt = 0; kt < 8; ++kt) {
            u32 aw[4];
            ldmx4(aw[0], aw[1], aw[2], aw[3], ldm[0] + kt * 32);
            mma16816(xa[0], aw, b0[kt]);
            ldmx4(aw[0], aw[1], aw[2], aw[3], ldm[1] + kt * 32);
            mma16816(xa[1], aw, b0[kt]);
        }
        // gates: i,f from published xg_if; g,o local
        const float gi0 = acc[0][0] + __bfloat162float(xb[r0 * XPI + u0]);
        const float gi1 = acc[0][1] + __bfloat162float(xb[r1 * XPI + u0]);
        const float gi2 = acc[0][2] + __bfloat162float(xb[r0 * XPI + u1]);
        const float gi3 = acc[0][3] + __bfloat162float(xb[r1 * XPI + u1]);
        const float gf0 = acc[1][0] + __bfloat162float(xb[r0 * XPI + 128 + u0]);
        const float gf1 = acc[1][1] + __bfloat162float(xb[r1 * XPI + 128 + u0]);
        const float gf2 = acc[1][2] + __bfloat162float(xb[r0 * XPI + 128 + u1]);
        const float gf3 = acc[1][3] + __bfloat162float(xb[r1 * XPI + 128 + u1]);
        const float gg0 = acc[2][0] + xa[0][0] + bg0;
        const float gg1 = acc[2][1] + xa[0][1] + bg0;
        const float gg2 = acc[2][2] + xa[0][2] + bg1;
        const float gg3 = acc[2][3] + xa[0][3] + bg1;
        const float go0 = acc[3][0] + xa[1][0] + bo0;
        const float go1 = acc[3][1] + xa[1][1] + bo0;
        const float go2 = acc[3][2] + xa[1][2] + bo1;
        const float go3 = acc[3][3] + xa[1][3] + bo1;
        float h[4];
        cst[0] = sigm(gf0) * cst[0] + sigm(gi0) * tanha(gg0);
        h[0] = sigm(go0) * tanha(cst[0]);
        cst[1] = sigm(gf1) * cst[1] + sigm(gi1) * tanha(gg1);
        h[1] = sigm(go1) * tanha(cst[1]);
        cst[2] = sigm(gf2) * cst[2] + sigm(gi2) * tanha(gg2);
        h[2] = sigm(go2) * tanha(cst[2]);
        cst[3] = sigm(gf3) * cst[3] + sigm(gi3) * tanha(gg3);
        h[3] = sigm(go3) * tanha(cst[3]);
        hn[r0 * PADH + u0] = __float2bfloat16(h[0]);
        hn[r1 * PADH + u0] = __float2bfloat16(h[1]);
        hn[r0 * PADH + u1] = __float2bfloat16(h[2]);
        hn[r1 * PADH + u1] = __float2bfloat16(h[3]);
        if (hasn) {
            __nv_bfloat16 *xn = xifbuf + ((t + 1) & 1) * ROWS * XPI;
            *(uint4 *)&xn[xrow * XPI + xseg * 8] = pfx;
            if (tid < 128) {
                __nv_bfloat16 *h0n = h0buf + ((t + 1) & 1) * ROWS * PADH;
                *(uint4 *)&h0n[hrow * PADH + hseg * 8] = pfh;
            }
        } else {
            g_h1f[(rb + r0) * HH + u0] = h[0];
            g_h1f[(rb + r1) * HH + u0] = h[1];
            g_h1f[(rb + r0) * HH + u1] = h[2];
            g_h1f[(rb + r1) * HH + u1] = h[3];
        }
        __syncthreads();
    }
}

extern "C" __global__ void __launch_bounds__(256, 1)
k_pipe(const float *__restrict__ x, const float *__restrict__ Wih0,
       const float *__restrict__ Whh0, const float *__restrict__ bih0,
       const float *__restrict__ bhh0, const float *__restrict__ Wih1,
       const float *__restrict__ Whh1, const float *__restrict__ bih1,
       const float *__restrict__ bhh1) {
    extern __shared__ char smem[];
    if (blockIdx.x < NPAIR)
        producer(x, Wih0, Whh0, bih0, bhh0, Wih1, bih1, bhh1, smem);
    else
        consumer(Whh1, Wih1, bih1, bhh1, smem);
}

extern "C" __global__ void k_reset() {
    if (threadIdx.x < NPAIR) g_flag[threadIdx.x] = 0u;
}

// ================= classifier MLP + double softmax =================
extern "C" __global__ void __launch_bounds__(128)
k_cls(const float *__restrict__ W1, const float *__restrict__ b1,
      const float *__restrict__ W2, const float *__restrict__ b2,
      const float *__restrict__ W3, const float *__restrict__ b3,
      float *__restrict__ out) {
    __shared__ float hb[128], z1[128], z2[64], z3[8];
    const int tid = threadIdx.x;
    const int row = blockIdx.x;
    hb[tid] = g_h1f[row * HH + tid];
    __syncthreads();
    float a = b1[tid];
#pragma unroll 4
    for (int k = 0; k < 128; ++k) a = fmaf(W1[tid * 128 + k], hb[k], a);
    z1[tid] = fmaxf(a, 0.f);
    __syncthreads();
    if (tid < 64) {
        float s = b2[tid];
#pragma unroll 4
        for (int k = 0; k < 128; ++k) s = fmaf(W2[tid * 128 + k], z1[k], s);
        z2[tid] = fmaxf(s, 0.f);
    }
    __syncthreads();
    if (tid < 6) {
        float s = b3[tid];
#pragma unroll 4
        for (int k = 0; k < 64; ++k) s = fmaf(W3[tid * 64 + k], z2[k], s);
        z3[tid] = s;
    }
    __syncthreads();
    if (tid == 0) {
        float v[6];
#pragma unroll
        for (int i = 0; i < 6; ++i) v[i] = z3[i];
#pragma unroll
        for (int p = 0; p < 2; ++p) {
            float m = v[0];
            for (int i = 1; i < 6; ++i) m = fmaxf(m, v[i]);
            float s = 0.f;
            for (int i = 0; i < 6; ++i) { v[i] = expf(v[i] - m); s += v[i]; }
            float inv = 1.f / s;
            for (int i = 0; i < 6; ++i) v[i] *= inv;
        }
        for (int i = 0; i < 6; ++i) out[row * 6 + i] = v[i];
    }
}

extern "C" void kernel_launch(void *const *d_in, const int *in_sizes, int n_in,
                              void *d_out, int out_size) {
    const float *x = (const float *)d_in[0];
    const float *Wih0 = (const float *)d_in[1];
    const float *Whh0 = (const float *)d_in[2];
    const float *bih0 = (const float *)d_in[3];
    const float *bhh0 = (const float *)d_in[4];
    const float *Wih1 = (const float *)d_in[5];
    const float *Whh1 = (const float *)d_in[6];
    const float *bih1 = (const float *)d_in[7];
    const float *bhh1 = (const float *)d_in[8];
    const float *W1 = (const float *)d_in[9];
    const float *b1 = (const float *)d_in[10];
    const float *W2 = (const float *)d_in[11];
    const float *b2 = (const float *)d_in[12];
    const float *W3 = (const float *)d_in[13];
    const float *b3 = (const float *)d_in[14];
    float *out = (float *)d_out;

    const int SMEMP = 17152 + 69632;  // 86784: max(producer 82496, consumer 86784)
    cudaFuncSetAttribute(k_pipe, cudaFuncAttributeMaxDynamicSharedMemorySize, SMEMP);

    k_reset<<<1, 64>>>();
    k_pipe<<<2 * NPAIR, 256, SMEMP>>>(x, Wih0, Whh0, bih0, bhh0, Wih1, Whh1, bih1, bhh1);
    k_cls<<<BB, 128>>>(W1, b1, W2, b2, W3, b3, out);
}